// round 3
// baseline (speedup 1.0000x reference)
#include <cuda_runtime.h>
#include <cuda_bf16.h>
#include <cstdint>

// out = (((x+2)*3 - 5)/4)^2 = ((3x+1)/4)^2 ; t = fma(0.75, x, 0.25), out = t*t
// 64M fp32, pure HBM streaming. 4x float4 per thread, front-batched loads
// (MLP_p1 = 4), streaming cache hints on both load and store.

__global__ __launch_bounds__(256) void ewise_sq_kernel(
    const float4* __restrict__ in, float4* __restrict__ out, int n4)
{
    const int base = blockIdx.x * (blockDim.x * 4) + threadIdx.x;
    const int s = blockDim.x;

    // n4 = 16777216 is exactly divisible by 1024 per block, so for the
    // exact launch below all 4 accesses are in-bounds; keep guard for safety.
    if (base + 3 * s < n4) {
        // Front-batch all 4 loads -> 4 outstanding LDG.128 per thread.
        float4 a0 = __ldcs(&in[base]);
        float4 a1 = __ldcs(&in[base + s]);
        float4 a2 = __ldcs(&in[base + 2 * s]);
        float4 a3 = __ldcs(&in[base + 3 * s]);

        float4 r0, r1, r2, r3;
        #define EW(dst, src) do {                       \
            float t0 = fmaf(0.75f, (src).x, 0.25f);     \
            float t1 = fmaf(0.75f, (src).y, 0.25f);     \
            float t2 = fmaf(0.75f, (src).z, 0.25f);     \
            float t3 = fmaf(0.75f, (src).w, 0.25f);     \
            (dst).x = t0 * t0; (dst).y = t1 * t1;       \
            (dst).z = t2 * t2; (dst).w = t3 * t3;       \
        } while (0)
        EW(r0, a0); EW(r1, a1); EW(r2, a2); EW(r3, a3);

        __stcs(&out[base],         r0);
        __stcs(&out[base + s],     r1);
        __stcs(&out[base + 2 * s], r2);
        __stcs(&out[base + 3 * s], r3);
    } else {
        for (int k = 0; k < 4; k++) {
            int i = base + k * s;
            if (i < n4) {
                float4 a = __ldcs(&in[i]);
                float4 r;
                EW(r, a);
                __stcs(&out[i], r);
            }
        }
        #undef EW
    }
}

extern "C" void kernel_launch(void* const* d_in, const int* in_sizes, int n_in,
                              void* d_out, int out_size)
{
    const float* x = (const float*)d_in[0];
    float* y = (float*)d_out;
    int n = in_sizes[0];      // 67108864
    int n4 = n >> 2;          // 16777216 float4

    const int threads = 256;
    const int per_block = threads * 4;                 // 1024 float4 / block
    int blocks = (n4 + per_block - 1) / per_block;     // 16384 blocks

    ewise_sq_kernel<<<blocks, threads>>>((const float4*)x, (float4*)y, n4);
}